// round 13
// baseline (speedup 1.0000x reference)
#include <cuda_runtime.h>
#include <math.h>

// ---------------------------------------------------------------------------
// att_lstm round 13: round-9 champion verbatim (tf32 mma.sync, 32x64 warp
// tiles, CTA 128x128, 2 CTAs/SM, 3-stage cp.async, 1 barrier/iter, ln_rows
// restored) + conv_concat pass DELETED: GEMM-1 reads the 4 modality tensors
// directly via LDG+cvt.rna+STS in its A loader (tgemm_fus). Bit-identical
// smem operands => rel_err unchanged.
// ---------------------------------------------------------------------------

#define B_    2048
#define SEQ_  16
#define DIM_  1024
#define HID_  512
#define DK_   512
#define NH_   4
#define DH_   128
#define G4_   (4 * HID_)      // 2048
#define BS_   (B_ * SEQ_)     // 32768
#define EPS_  1e-5f

#define MT 128
#define NT 128
#define BK 32
#define ASTR 36                       // A smem row stride (floats)
#define ABYTES (128 * ASTR * 4)       // 18432
#define BBYTES (2 * 16 * 512)         // 16384 per stage
#define STG (ABYTES + BBYTES)         // 34816
#define NSTG 3
#define SMEM_G (NSTG * STG)           // 104448

// ------------------------------- scratch -----------------------------------
__device__ float d_fusWp[4096 * DIM_];
__device__ float d_Wihp [G4_ * DIM_];
__device__ float d_Whhp [G4_ * HID_];
__device__ float d_wqp  [DK_ * HID_];
__device__ float d_wkp  [DK_ * HID_];
__device__ float d_wvp  [NH_ * DK_ * HID_];
__device__ float d_woutp[DK_ * NH_ * DK_];
__device__ float d_vt  [(long)BS_ * DIM_];
__device__ float d_gx  [(long)BS_ * G4_];
__device__ float d_hw  [B_  * G4_];
__device__ float d_h   [B_  * HID_];
__device__ float d_c   [B_  * HID_];
__device__ float d_lstm[(long)BS_ * HID_];
__device__ float d_kall[(long)BS_ * DK_];
__device__ float d_qb  [B_  * DK_];
__device__ float d_m   [B_  * NH_ * HID_];
__device__ float d_ctx [B_  * NH_ * DK_];
__device__ float d_oh  [B_  * DK_];
__device__ float d_diff[B_];

// --------------------------- helpers ---------------------------------------
__device__ __forceinline__ float sigm(float x) { return 1.0f / (1.0f + expf(-x)); }

__device__ __forceinline__ float f2tf(float f) {
    unsigned u;
    asm("cvt.rna.tf32.f32 %0, %1;" : "=r"(u) : "f"(f));
    return __uint_as_float(u);
}

__device__ __forceinline__ void cpa16(unsigned dst, const void* src) {
    asm volatile("cp.async.cg.shared.global [%0], [%1], 16;\n" :: "r"(dst), "l"(src));
}
__device__ __forceinline__ void cpa_commit() { asm volatile("cp.async.commit_group;\n"); }
__device__ __forceinline__ void cpa_wait1()  { asm volatile("cp.async.wait_group 1;\n"); }

__device__ __forceinline__ void ldm4(unsigned* r, unsigned addr) {
    asm volatile("ldmatrix.sync.aligned.m8n8.x4.shared.b16 {%0,%1,%2,%3}, [%4];"
        : "=r"(r[0]), "=r"(r[1]), "=r"(r[2]), "=r"(r[3]) : "r"(addr));
}

__device__ __forceinline__ void lds2(unsigned& a, unsigned& b, unsigned addr) {
    asm volatile("ld.shared.v2.b32 {%0,%1}, [%2];" : "=r"(a), "=r"(b) : "r"(addr));
}

__device__ __forceinline__ void mma_tf32(float* c, const unsigned* a,
                                         unsigned b0, unsigned b1) {
    asm volatile(
        "mma.sync.aligned.m16n8k8.row.col.f32.tf32.tf32.f32 "
        "{%0,%1,%2,%3},{%4,%5,%6,%7},{%8,%9},{%0,%1,%2,%3};\n"
        : "+f"(c[0]), "+f"(c[1]), "+f"(c[2]), "+f"(c[3])
        : "r"(a[0]), "r"(a[1]), "r"(a[2]), "r"(a[3]), "r"(b0), "r"(b1));
}

__device__ __forceinline__ float2 blockReduce2(float a, float b) {
    __shared__ float s1[8], s2[8];
    const unsigned m = 0xffffffffu;
    #pragma unroll
    for (int o = 16; o > 0; o >>= 1) {
        a += __shfl_down_sync(m, a, o);
        b += __shfl_down_sync(m, b, o);
    }
    int w = threadIdx.x >> 5, l = threadIdx.x & 31;
    if (l == 0) { s1[w] = a; s2[w] = b; }
    __syncthreads();
    int nw = blockDim.x >> 5;
    if (w == 0) {
        a = (l < nw) ? s1[l] : 0.0f;
        b = (l < nw) ? s2[l] : 0.0f;
        #pragma unroll
        for (int o = 4; o > 0; o >>= 1) {
            a += __shfl_down_sync(m, a, o);
            b += __shfl_down_sync(m, b, o);
        }
        if (l == 0) { s1[0] = a; s2[0] = b; }
    }
    __syncthreads();
    float2 r = make_float2(s1[0], s2[0]);
    __syncthreads();
    return r;
}

// ------------------------ producers ----------------------------------------
// permute weight (N,K) row-major into mma-fragment order, tf32-rounded.
__global__ void __launch_bounds__(256)
perm_w(const float* __restrict__ W, float* __restrict__ P, int N, int K)
{
    long i = (long)blockIdx.x * 256 + threadIdx.x;
    long n = (long)N * K;
    if (i >= n) return;
    int k = (int)(i % K);
    int nn = (int)(i / K);
    int kg = k >> 4, nt = nn >> 3;
    int q2 = (k >> 3) & 1, pos = (k >> 2) & 1;
    int l = (nn & 7) * 4 + (k & 3);
    long o = ((((long)kg * (N >> 3) + nt) * 2 + q2) * 64) + l * 2 + pos;
    P[o] = f2tf(W[i]);
}

__global__ void __launch_bounds__(256)
round_vec(const float* __restrict__ s, float* __restrict__ d, long n)
{
    long i = (long)blockIdx.x * 256 + threadIdx.x;
    if (i < n) d[i] = f2tf(s[i]);
}

// --------------------------- tf32 GEMM (round-9 champion) -------------------
__global__ void __launch_bounds__(256, 2)
tgemm(const float* __restrict__ A, int lda, long sAz,
      const float* __restrict__ Bp, long sBz, int N,
      float* __restrict__ C, int ldc, long sCz, int K,
      const float* __restrict__ bias, int sbz, int act, int rnd)
{
    extern __shared__ __align__(16) float dsm[];
    const int tid = threadIdx.x;
    const int m0 = blockIdx.y * MT;
    const int nt0 = blockIdx.x * 16;
    A  += (long)blockIdx.z * sAz;
    Bp += (long)blockIdx.z * sBz;
    C  += (long)blockIdx.z * sCz;
    const float* bz = bias ? bias + (long)blockIdx.z * sbz : (const float*)0;

    const int w = tid >> 5, lane = tid & 31;
    const int wm = w & 3, wn = w >> 2;
    const int gid = lane >> 2, tig = lane & 3;

    const unsigned sb = (unsigned)__cvta_generic_to_shared(dsm);
    const int NT8 = N >> 3;

    float acc[2][8][4];
    #pragma unroll
    for (int i = 0; i < 2; i++)
        #pragma unroll
        for (int j = 0; j < 8; j++)
            #pragma unroll
            for (int q = 0; q < 4; q++) acc[i][j][q] = 0.0f;

    const int KT = K / BK;

    const int ar = tid >> 3, ach = tid & 7;
    auto loadStage = [&](int stg, int k0) {
        const unsigned as = sb + (unsigned)stg * STG;
        #pragma unroll
        for (int i = 0; i < 4; i++) {
            int r = ar + i * 32;
            cpa16(as + (unsigned)(r * ASTR * 4 + ach * 16),
                  A + (long)(m0 + r) * lda + k0 + ach * 4);
        }
        const unsigned bs = as + ABYTES;
        const int kg0 = k0 >> 4;
        #pragma unroll
        for (int i = 0; i < 4; i++) {
            int g = i * 256 + tid;
            int kg2 = g >> 9, rest = g & 511;
            cpa16(bs + (unsigned)(kg2 * 8192 + rest * 16),
                  Bp + ((long)(kg0 + kg2) * NT8 + nt0) * 128 + rest * 4);
        }
    };

    loadStage(0, 0);
    cpa_commit();
    if (KT > 1) loadStage(1, BK);
    cpa_commit();

    const unsigned aoffL = (unsigned)((wm * 32 + (lane & 15)) * ASTR * 4 + (lane >> 4) * 16);
    const unsigned boffL = (unsigned)((wn * 8) * 512 + lane * 8);

    int stage = 0;
    for (int t = 0; t < KT; t++) {
        cpa_wait1();
        __syncthreads();
        const unsigned as = sb + (unsigned)stage * STG;
        const unsigned bs = as + ABYTES;
        #pragma unroll
        for (int kk = 0; kk < 4; kk++) {
            unsigned af0[4], af1[4];
            ldm4(af0, as + aoffL + kk * 32);
            ldm4(af1, as + aoffL + 16 * ASTR * 4 + kk * 32);
            const unsigned bb = bs + boffL + (kk >> 1) * 8192 + (kk & 1) * 256;
            #pragma unroll
            for (int j = 0; j < 8; j++) {
                unsigned b0, b1;
                lds2(b0, b1, bb + j * 512);
                mma_tf32(acc[0][j], af0, b0, b1);
                mma_tf32(acc[1][j], af1, b0, b1);
            }
        }
        if (t + 2 < KT) {
            int ns = stage + 2; if (ns >= NSTG) ns -= NSTG;
            loadStage(ns, (t + 2) * BK);
        }
        cpa_commit();
        if (++stage == NSTG) stage = 0;
    }

    const int n0 = nt0 * 8;
    #pragma unroll
    for (int i = 0; i < 2; i++) {
        const int r0 = m0 + wm * 32 + i * 16 + gid;
        #pragma unroll
        for (int j = 0; j < 8; j++) {
            const int col = n0 + wn * 64 + j * 8 + 2 * tig;
            float bx = 0.0f, by = 0.0f;
            if (bz) { bx = bz[col]; by = bz[col + 1]; }
            float v0x = acc[i][j][0] + bx, v0y = acc[i][j][1] + by;
            float v1x = acc[i][j][2] + bx, v1y = acc[i][j][3] + by;
            if (act) {
                v0x = fmaxf(v0x, 0.0f); v0y = fmaxf(v0y, 0.0f);
                v1x = fmaxf(v1x, 0.0f); v1y = fmaxf(v1y, 0.0f);
            }
            if (rnd) {
                v0x = f2tf(v0x); v0y = f2tf(v0y);
                v1x = f2tf(v1x); v1y = f2tf(v1y);
            }
            *(float2*)(C + (long)r0 * ldc + col) = make_float2(v0x, v0y);
            *(float2*)(C + (long)(r0 + 8) * ldc + col) = make_float2(v1x, v1y);
        }
    }
}

// --------------- GEMM-1 specialization: virtual-concat A --------------------
// A = [visual|text|user|cat] along K (4096); A loaded via LDG + cvt.rna + STS
// (bit-identical smem values to the old conv_concat + cp.async path).
// B = fusWp (permuted), N=1024, K=4096, bias+relu+round epilogue.
__global__ void __launch_bounds__(256, 2)
tgemm_fus(const float* __restrict__ p0, const float* __restrict__ p1,
          const float* __restrict__ p2, const float* __restrict__ p3,
          const float* __restrict__ Bp,
          float* __restrict__ C, const float* __restrict__ bias)
{
    extern __shared__ __align__(16) float dsm[];
    const int tid = threadIdx.x;
    const int m0 = blockIdx.y * MT;
    const int nt0 = blockIdx.x * 16;
    const int K = 4096, N = DIM_;

    const int w = tid >> 5, lane = tid & 31;
    const int wm = w & 3, wn = w >> 2;
    const int gid = lane >> 2, tig = lane & 3;

    const unsigned sb = (unsigned)__cvta_generic_to_shared(dsm);
    const int NT8 = N >> 3;

    float acc[2][8][4];
    #pragma unroll
    for (int i = 0; i < 2; i++)
        #pragma unroll
        for (int j = 0; j < 8; j++)
            #pragma unroll
            for (int q = 0; q < 4; q++) acc[i][j][q] = 0.0f;

    const int KT = K / BK;

    const int ar = tid >> 3, ach = tid & 7;
    auto loadStage = [&](int stg, int k0) {
        // A: LDG from segment-selected modality pointer (strip of 32 k's never
        // crosses a 1024 segment boundary), issued first to overlap with the
        // B cp.async batch below; cvt+STS after.
        const int k = k0 + ach * 4;
        const int seg = k >> 10, kl = k & 1023;
        const float* p = (seg == 0) ? p0 : (seg == 1) ? p1 : (seg == 2) ? p2 : p3;
        float4 va[4];
        #pragma unroll
        for (int i = 0; i < 4; i++) {
            int r = ar + i * 32;
            va[i] = *(const float4*)(p + (long)(m0 + r) * DIM_ + kl);
        }
        // B: cp.async (unchanged from champion)
        const unsigned as = sb + (unsigned)stg * STG;
        const unsigned bs = as + ABYTES;
        const int kg0 = k0 >> 4;
        #pragma unroll
        for (int i = 0; i < 4; i++) {
            int g = i * 256 + tid;
            int kg2 = g >> 9, rest = g & 511;
            cpa16(bs + (unsigned)(kg2 * 8192 + rest * 16),
                  Bp + ((long)(kg0 + kg2) * NT8 + nt0) * 128 + rest * 4);
        }
        // A: cvt + STS
        float* asf = dsm + (long)stg * (STG / 4);
        #pragma unroll
        for (int i = 0; i < 4; i++) {
            int r = ar + i * 32;
            float4 v = va[i];
            v.x = f2tf(v.x); v.y = f2tf(v.y); v.z = f2tf(v.z); v.w = f2tf(v.w);
            *(float4*)(asf + r * ASTR + ach * 4) = v;
        }
    };

    loadStage(0, 0);
    cpa_commit();
    loadStage(1, BK);
    cpa_commit();

    const unsigned aoffL = (unsigned)((wm * 32 + (lane & 15)) * ASTR * 4 + (lane >> 4) * 16);
    const unsigned boffL = (unsigned)((wn * 8) * 512 + lane * 8);

    int stage = 0;
    for (int t = 0; t < KT; t++) {
        cpa_wait1();
        __syncthreads();
        const unsigned as = sb + (unsigned)stage * STG;
        const unsigned bs = as + ABYTES;
        #pragma unroll
        for (int kk = 0; kk < 4; kk++) {
            unsigned af0[4], af1[4];
            ldm4(af0, as + aoffL + kk * 32);
            ldm4(af1, as + aoffL + 16 * ASTR * 4 + kk * 32);
            const unsigned bb = bs + boffL + (kk >> 1) * 8192 + (kk & 1) * 256;
            #pragma unroll
            for (int j = 0; j < 8; j++) {
                unsigned b0, b1;
                lds2(b0, b1, bb + j * 512);
                mma_tf32(acc[0][j], af0, b0, b1);
                mma_tf32(acc[1][j], af1, b0, b1);
            }
        }
        if (t + 2 < KT) {
            int ns = stage + 2; if (ns >= NSTG) ns -= NSTG;
            loadStage(ns, (t + 2) * BK);
        }
        cpa_commit();
        if (++stage == NSTG) stage = 0;
    }

    const int n0 = nt0 * 8;
    #pragma unroll
    for (int i = 0; i < 2; i++) {
        const int r0 = m0 + wm * 32 + i * 16 + gid;
        #pragma unroll
        for (int j = 0; j < 8; j++) {
            const int col = n0 + wn * 64 + j * 8 + 2 * tig;
            float bx = bias[col], by = bias[col + 1];
            float v0x = fmaxf(acc[i][j][0] + bx, 0.0f);
            float v0y = fmaxf(acc[i][j][1] + by, 0.0f);
            float v1x = fmaxf(acc[i][j][2] + bx, 0.0f);
            float v1y = fmaxf(acc[i][j][3] + by, 0.0f);
            v0x = f2tf(v0x); v0y = f2tf(v0y);
            v1x = f2tf(v1x); v1y = f2tf(v1y);
            *(float2*)(C + (long)r0 * DIM_ + col) = make_float2(v0x, v0y);
            *(float2*)(C + (long)(r0 + 8) * DIM_ + col) = make_float2(v1x, v1y);
        }
    }
}

// --------------------- pointwise kernels (round-9 versions) -----------------
__global__ void __launch_bounds__(256)
ln_rows_kernel(float* __restrict__ x, const float* __restrict__ g,
               const float* __restrict__ b)
{
    __shared__ float sx[G4_];
    long base = (long)blockIdx.x * G4_;
    float s = 0.0f, ss = 0.0f;
    for (int j = threadIdx.x; j < G4_; j += 256) {
        float v = x[base + j];
        sx[j] = v; s += v; ss += v * v;
    }
    float2 r = blockReduce2(s, ss);
    float mean = r.x * (1.0f / G4_);
    float var  = r.y * (1.0f / G4_) - mean * mean;
    float inv  = rsqrtf(var + EPS_);
    for (int j = threadIdx.x; j < G4_; j += 256)
        x[base + j] = (sx[j] - mean) * inv * g[j] + b[j];
}

__global__ void __launch_bounds__(256)
lstm_cell_kernel(const float* __restrict__ hw,
                 const float* __restrict__ gx,
                 const float* __restrict__ g_hh, const float* __restrict__ b_hh,
                 const float* __restrict__ g_c,  const float* __restrict__ b_c,
                 float* __restrict__ h, float* __restrict__ c,
                 float* __restrict__ lstm, int t)
{
    __shared__ float sg[G4_];
    const int b = blockIdx.x;
    const int tid = threadIdx.x;
    const float* row = hw + (long)b * G4_;
    float s = 0.0f, ss = 0.0f;
    for (int j = tid; j < G4_; j += 256) {
        float v = row[j];
        sg[j] = v; s += v; ss += v * v;
    }
    float2 r = blockReduce2(s, ss);
    float mean = r.x * (1.0f / G4_);
    float var  = r.y * (1.0f / G4_) - mean * mean;
    float inv  = rsqrtf(var + EPS_);

    const float* gxr = gx + ((long)b * SEQ_ + t) * G4_;
    float cval[2];
    float sc = 0.0f, ssc = 0.0f;
    #pragma unroll
    for (int rr = 0; rr < 2; rr++) {
        int j = rr * 256 + tid;
        float gi = (sg[j]        - mean) * inv * g_hh[j]        + b_hh[j]        + gxr[j];
        float gf = (sg[512 + j]  - mean) * inv * g_hh[512 + j]  + b_hh[512 + j]  + gxr[512 + j];
        float gg = (sg[1024 + j] - mean) * inv * g_hh[1024 + j] + b_hh[1024 + j] + gxr[1024 + j];
        float cn = sigm(gf) * c[(long)b * HID_ + j] + sigm(gi) * tanhf(gg);
        cval[rr] = cn;
        c[(long)b * HID_ + j] = cn;
        sc += cn; ssc += cn * cn;
    }
    float2 rc = blockReduce2(sc, ssc);
    float meanc = rc.x * (1.0f / HID_);
    float varc  = rc.y * (1.0f / HID_) - meanc * meanc;
    float invc  = rsqrtf(varc + EPS_);
    #pragma unroll
    for (int rr = 0; rr < 2; rr++) {
        int j = rr * 256 + tid;
        float go = (sg[1536 + j] - mean) * inv * g_hh[1536 + j] + b_hh[1536 + j] + gxr[1536 + j];
        float hn = sigm(go) * tanhf((cval[rr] - meanc) * invc * g_c[j] + b_c[j]);
        hn = f2tf(hn);
        h[(long)b * HID_ + j] = hn;
        lstm[((long)b * SEQ_ + t) * HID_ + j] = hn;
    }
}

__global__ void __launch_bounds__(128)
attn_kernel(const float* __restrict__ kall, const float* __restrict__ qb,
            const float* __restrict__ lstm, float* __restrict__ mbuf)
{
    const int hidx = blockIdx.x;
    const int b    = blockIdx.y;
    const int tid  = threadIdx.x;
    __shared__ float ssc[SEQ_];
    __shared__ float wsum[SEQ_][4];

    float qv = qb[(long)b * DK_ + hidx * DH_ + tid];
    int w = tid >> 5, l = tid & 31;
    for (int s = 0; s < SEQ_; s++) {
        float v = kall[((long)b * SEQ_ + s) * DK_ + hidx * DH_ + tid] * qv;
        #pragma unroll
        for (int o = 16; o > 0; o >>= 1) v += __shfl_down_sync(0xffffffffu, v, o);
        if (l == 0) wsum[s][w] = v;
    }
    __syncthreads();
    if (tid < SEQ_) {
        float sc = wsum[tid][0] + wsum[tid][1] + wsum[tid][2] + wsum[tid][3];
        ssc[tid] = sc * 0.08838834764831845f;
    }
    __syncthreads();

    float e[SEQ_];
    float mx = -1e30f;
    #pragma unroll
    for (int s = 0; s < SEQ_; s++) mx = fmaxf(mx, ssc[s]);
    float den = 0.0f;
    #pragma unroll
    for (int s = 0; s < SEQ_; s++) { e[s] = expf(ssc[s] - mx); den += e[s]; }
    float dinv = 1.0f / den;

    #pragma unroll
    for (int rr = 0; rr < HID_ / 128; rr++) {
        int d = rr * 128 + tid;
        float acc = 0.0f;
        #pragma unroll
        for (int s = 0; s < SEQ_; s++)
            acc += e[s] * lstm[((long)b * SEQ_ + s) * HID_ + d];
        mbuf[((long)b * NH_ + hidx) * HID_ + d] = f2tf(acc * dinv);
    }
}

__global__ void __launch_bounds__(256)
out_final_kernel(const float* __restrict__ oh, const float* __restrict__ outW,
                 const float* __restrict__ outb, const float* __restrict__ label,
                 float* __restrict__ out, float* __restrict__ diff)
{
    int w = threadIdx.x >> 5, l = threadIdx.x & 31;
    int b = blockIdx.x * 8 + w;
    float s = 0.0f;
    for (int j = l; j < DK_; j += 32) s += oh[(long)b * DK_ + j] * outW[j];
    #pragma unroll
    for (int o = 16; o > 0; o >>= 1) s += __shfl_down_sync(0xffffffffu, s, o);
    if (l == 0) {
        float v = s + outb[0];
        out[1 + b] = v;
        float d = v - label[(long)b * SEQ_ + (SEQ_ - 1)];
        diff[b] = d * d;
    }
}

__global__ void __launch_bounds__(256)
loss_kernel(const float* __restrict__ diff, float* __restrict__ out)
{
    float s = 0.0f;
    for (int j = threadIdx.x; j < B_; j += 256) s += diff[j];
    float2 r = blockReduce2(s, 0.0f);
    if (threadIdx.x == 0) out[0] = r.x * (1.0f / B_);
}

// ------------------------------- launch -------------------------------------
static inline void getp(void** p, const void* sym) { cudaGetSymbolAddress(p, sym); }

extern "C" void kernel_launch(void* const* d_in, const int* in_sizes, int n_in,
                              void* d_out, int out_size)
{
    const float* visual = (const float*)d_in[0];
    const float* text   = (const float*)d_in[1];
    const float* user   = (const float*)d_in[2];
    const float* cat    = (const float*)d_in[3];
    const float* label  = (const float*)d_in[4];
    const float* h0     = (const float*)d_in[5];
    const float* c0     = (const float*)d_in[6];
    const float* fus_W  = (const float*)d_in[7];
    const float* fus_b  = (const float*)d_in[8];
    const float* W_ih   = (const float*)d_in[9];
    const float* W_hh   = (const float*)d_in[10];
    const float* g_ih   = (const float*)d_in[11];
    const float* b_ih   = (const float*)d_in[12];
    const float* g_hh   = (const float*)d_in[13];
    const float* b_hh   = (const float*)d_in[14];
    const float* g_c    = (const float*)d_in[15];
    const float* b_c    = (const float*)d_in[16];
    const float* wq_W   = (const float*)d_in[17];
    const float* wq_b   = (const float*)d_in[18];
    const float* wk_W   = (const float*)d_in[19];
    const float* wk_b   = (const float*)d_in[20];
    const float* wv_W   = (const float*)d_in[21];
    const float* wv_b   = (const float*)d_in[22];
    const float* wout_W = (const float*)d_in[23];
    const float* wout_b = (const float*)d_in[24];
    const float* out_W  = (const float*)d_in[25];
    const float* out_b  = (const float*)d_in[26];
    float* out = (float*)d_out;

    float *fusWp, *Wihp, *Whhp, *wqp, *wkp, *wvp, *woutp;
    float *vt, *gx, *hw, *h, *c, *lstm, *kall, *qb, *m, *ctx, *oh, *diff;
    getp((void**)&fusWp, d_fusWp);
    getp((void**)&Wihp,  d_Wihp);  getp((void**)&Whhp,  d_Whhp);
    getp((void**)&wqp,   d_wqp);   getp((void**)&wkp,   d_wkp);
    getp((void**)&wvp,   d_wvp);   getp((void**)&woutp, d_woutp);
    getp((void**)&vt,    d_vt);    getp((void**)&gx,    d_gx);
    getp((void**)&hw,    d_hw);    getp((void**)&h,     d_h);
    getp((void**)&c,     d_c);     getp((void**)&lstm,  d_lstm);
    getp((void**)&kall,  d_kall);  getp((void**)&qb,    d_qb);
    getp((void**)&m,     d_m);     getp((void**)&ctx,   d_ctx);
    getp((void**)&oh,    d_oh);    getp((void**)&diff,  d_diff);

    cudaFuncSetAttribute(tgemm, cudaFuncAttributeMaxDynamicSharedMemorySize, SMEM_G);
    cudaFuncSetAttribute(tgemm_fus, cudaFuncAttributeMaxDynamicSharedMemorySize, SMEM_G);

    // 0. producers: permute+round weights, round h0 (no conv_concat pass)
    auto pw = [](const float* W, float* P, int N, int K) {
        long n = (long)N * K;
        perm_w<<<(unsigned)((n + 255) / 256), 256>>>(W, P, N, K);
    };
    pw(fus_W,  fusWp, DIM_, 4096);
    pw(W_ih,   Wihp,  G4_,  DIM_);
    pw(W_hh,   Whhp,  G4_,  HID_);
    pw(wq_W,   wqp,   DK_,  HID_);
    pw(wk_W,   wkp,   DK_,  HID_);
    for (int z = 0; z < NH_; z++)
        pw(wv_W + (long)z * DK_ * HID_, wvp + (long)z * DK_ * HID_, DK_, HID_);
    pw(wout_W, woutp, DK_,  NH_ * DK_);
    round_vec<<<(B_ * HID_ + 255) / 256, 256>>>(h0, h, (long)B_ * HID_);
    cudaMemcpyAsync(c, c0, (size_t)B_ * HID_ * sizeof(float), cudaMemcpyDeviceToDevice, 0);

    // 1. fusion GEMM + relu -> vt (rounded); A = virtual concat, in-loader cvt
    tgemm_fus<<<dim3(DIM_ / NT, BS_ / MT), 256, SMEM_G>>>(
        visual, text, user, cat, fusWp, vt, fus_b);

    // 2. gx = vt @ W_ih^T  (32768 x 2048 x 1024), then LN
    tgemm<<<dim3(G4_ / NT, BS_ / MT), 256, SMEM_G>>>(
        vt, DIM_, 0, Wihp, 0, G4_, gx, G4_, 0, DIM_, (const float*)0, 0, 0, 0);
    ln_rows_kernel<<<BS_, 256>>>(gx, g_ih, b_ih);

    // 3. LSTM recurrence
    for (int t = 0; t < SEQ_; t++) {
        tgemm<<<dim3(G4_ / NT, B_ / MT), 256, SMEM_G>>>(
            h, HID_, 0, Whhp, 0, G4_, hw, G4_, 0, HID_, (const float*)0, 0, 0, 0);
        lstm_cell_kernel<<<B_, 256>>>(hw, gx, g_hh, b_hh, g_c, b_c, h, c, lstm, t);
    }

    // 4. k / q projections
    tgemm<<<dim3(DK_ / NT, BS_ / MT), 256, SMEM_G>>>(
        lstm, HID_, 0, wkp, 0, DK_, kall, DK_, 0, HID_, wk_b, 0, 0, 0);
    tgemm<<<dim3(DK_ / NT, B_ / MT), 256, SMEM_G>>>(
        h, HID_, 0, wqp, 0, DK_, qb, DK_, 0, HID_, wq_b, 0, 0, 0);

    // 5. attention -> m (rounded)
    attn_kernel<<<dim3(NH_, B_), 128>>>(kall, qb, lstm, m);

    // 6. ctx = wv_W . m  (batched over heads, rounded)
    tgemm<<<dim3(DK_ / NT, B_ / MT, NH_), 256, SMEM_G>>>(
        m, NH_ * HID_, HID_, wvp, (long)DK_ * HID_, DK_,
        ctx, NH_ * DK_, DK_, HID_, wv_b, DK_, 0, 1);

    // 7. out_h = ctx @ wout_W^T  (2048 x 512 x 2048)
    tgemm<<<dim3(DK_ / NT, B_ / MT), 256, SMEM_G>>>(
        ctx, NH_ * DK_, 0, woutp, 0, DK_, oh, DK_, 0, NH_ * DK_, wout_b, 0, 0, 0);

    // 8. final projection + loss
    out_final_kernel<<<B_ / 8, 256>>>(oh, out_W, out_b, label, out, diff);
    loss_kernel<<<1, 256>>>(diff, out);
}

// round 14
// speedup vs baseline: 1.0519x; 1.0519x over previous
#include <cuda_runtime.h>
#include <math.h>

// ---------------------------------------------------------------------------
// att_lstm round 14: round-9 champion verbatim (tf32 mma.sync, 32x64 warp
// tiles, CTA 128x128, 2 CTAs/SM, 3-stage cp.async, 1 barrier/iter,
// conv_concat + ln_rows restored). Changes: (a) 9 perm_w launches merged into
// one perm_all kernel (bit-identical outputs); (b) ln_rows moved after the
// first LSTM GEMM so ncu -s 5 captures a tgemm launch.
// ---------------------------------------------------------------------------

#define B_    2048
#define SEQ_  16
#define DIM_  1024
#define HID_  512
#define DK_   512
#define NH_   4
#define DH_   128
#define G4_   (4 * HID_)      // 2048
#define BS_   (B_ * SEQ_)     // 32768
#define EPS_  1e-5f

#define MT 128
#define NT 128
#define BK 32
#define ASTR 36                       // A smem row stride (floats)
#define ABYTES (128 * ASTR * 4)       // 18432
#define BBYTES (2 * 16 * 512)         // 16384 per stage
#define STG (ABYTES + BBYTES)         // 34816
#define NSTG 3
#define SMEM_G (NSTG * STG)           // 104448

// ------------------------------- scratch -----------------------------------
__device__ float d_mods [(long)BS_ * 4096];
__device__ float d_fusWp[4096 * DIM_];
__device__ float d_Wihp [G4_ * DIM_];
__device__ float d_Whhp [G4_ * HID_];
__device__ float d_wqp  [DK_ * HID_];
__device__ float d_wkp  [DK_ * HID_];
__device__ float d_wvp  [NH_ * DK_ * HID_];
__device__ float d_woutp[DK_ * NH_ * DK_];
__device__ float d_vt  [(long)BS_ * DIM_];
__device__ float d_gx  [(long)BS_ * G4_];
__device__ float d_hw  [B_  * G4_];
__device__ float d_h   [B_  * HID_];
__device__ float d_c   [B_  * HID_];
__device__ float d_lstm[(long)BS_ * HID_];
__device__ float d_kall[(long)BS_ * DK_];
__device__ float d_qb  [B_  * DK_];
__device__ float d_m   [B_  * NH_ * HID_];
__device__ float d_ctx [B_  * NH_ * DK_];
__device__ float d_oh  [B_  * DK_];
__device__ float d_diff[B_];

// --------------------------- helpers ---------------------------------------
__device__ __forceinline__ float sigm(float x) { return 1.0f / (1.0f + expf(-x)); }

__device__ __forceinline__ float f2tf(float f) {
    unsigned u;
    asm("cvt.rna.tf32.f32 %0, %1;" : "=r"(u) : "f"(f));
    return __uint_as_float(u);
}

__device__ __forceinline__ void cpa16(unsigned dst, const void* src) {
    asm volatile("cp.async.cg.shared.global [%0], [%1], 16;\n" :: "r"(dst), "l"(src));
}
__device__ __forceinline__ void cpa_commit() { asm volatile("cp.async.commit_group;\n"); }
__device__ __forceinline__ void cpa_wait1()  { asm volatile("cp.async.wait_group 1;\n"); }

__device__ __forceinline__ void ldm4(unsigned* r, unsigned addr) {
    asm volatile("ldmatrix.sync.aligned.m8n8.x4.shared.b16 {%0,%1,%2,%3}, [%4];"
        : "=r"(r[0]), "=r"(r[1]), "=r"(r[2]), "=r"(r[3]) : "r"(addr));
}

__device__ __forceinline__ void lds2(unsigned& a, unsigned& b, unsigned addr) {
    asm volatile("ld.shared.v2.b32 {%0,%1}, [%2];" : "=r"(a), "=r"(b) : "r"(addr));
}

__device__ __forceinline__ void mma_tf32(float* c, const unsigned* a,
                                         unsigned b0, unsigned b1) {
    asm volatile(
        "mma.sync.aligned.m16n8k8.row.col.f32.tf32.tf32.f32 "
        "{%0,%1,%2,%3},{%4,%5,%6,%7},{%8,%9},{%0,%1,%2,%3};\n"
        : "+f"(c[0]), "+f"(c[1]), "+f"(c[2]), "+f"(c[3])
        : "r"(a[0]), "r"(a[1]), "r"(a[2]), "r"(a[3]), "r"(b0), "r"(b1));
}

__device__ __forceinline__ float2 blockReduce2(float a, float b) {
    __shared__ float s1[8], s2[8];
    const unsigned m = 0xffffffffu;
    #pragma unroll
    for (int o = 16; o > 0; o >>= 1) {
        a += __shfl_down_sync(m, a, o);
        b += __shfl_down_sync(m, b, o);
    }
    int w = threadIdx.x >> 5, l = threadIdx.x & 31;
    if (l == 0) { s1[w] = a; s2[w] = b; }
    __syncthreads();
    int nw = blockDim.x >> 5;
    if (w == 0) {
        a = (l < nw) ? s1[l] : 0.0f;
        b = (l < nw) ? s2[l] : 0.0f;
        #pragma unroll
        for (int o = 4; o > 0; o >>= 1) {
            a += __shfl_down_sync(m, a, o);
            b += __shfl_down_sync(m, b, o);
        }
        if (l == 0) { s1[0] = a; s2[0] = b; }
    }
    __syncthreads();
    float2 r = make_float2(s1[0], s2[0]);
    __syncthreads();
    return r;
}

// ------------------------ producers ----------------------------------------
__global__ void __launch_bounds__(256)
conv_concat(const float* __restrict__ p0, const float* __restrict__ p1,
            const float* __restrict__ p2, const float* __restrict__ p3,
            float* __restrict__ outp)
{
    long i = ((long)blockIdx.x * 256 + threadIdx.x) * 4;
    long n = (long)BS_ * 4096;
    if (i >= n) return;
    long r = i >> 12;
    int  c = (int)(i & 4095);
    int seg = c >> 10, cl = c & 1023;
    const float* p = (seg == 0) ? p0 : (seg == 1) ? p1 : (seg == 2) ? p2 : p3;
    float4 v = *(const float4*)(p + r * DIM_ + cl);
    v.x = f2tf(v.x); v.y = f2tf(v.y); v.z = f2tf(v.z); v.w = f2tf(v.w);
    *(float4*)(outp + i) = v;
}

// All weight permutes in ONE launch. Per-element math identical to perm_w.
#define SZ_FUS ((long)DIM_ * 4096)
#define SZ_IH  ((long)G4_ * DIM_)
#define SZ_HH  ((long)G4_ * HID_)
#define SZ_QK  ((long)DK_ * HID_)
#define SZ_WV  ((long)NH_ * DK_ * HID_)
#define SZ_OUT ((long)DK_ * NH_ * DK_)
__global__ void __launch_bounds__(256)
perm_all(const float* __restrict__ fus_W, const float* __restrict__ W_ih,
         const float* __restrict__ W_hh,  const float* __restrict__ wq_W,
         const float* __restrict__ wk_W,  const float* __restrict__ wv_W,
         const float* __restrict__ wout_W,
         float* __restrict__ fusWp, float* __restrict__ Wihp,
         float* __restrict__ Whhp,  float* __restrict__ wqp,
         float* __restrict__ wkp,   float* __restrict__ wvp,
         float* __restrict__ woutp)
{
    long i = (long)blockIdx.x * 256 + threadIdx.x;
    const long e0 = SZ_FUS, e1 = e0 + SZ_IH, e2 = e1 + SZ_HH, e3 = e2 + SZ_QK,
               e4 = e3 + SZ_QK, e5 = e4 + SZ_WV, e6 = e5 + SZ_OUT;
    if (i >= e6) return;
    const float* W; float* P; int N, K; long off;
    if (i < e0)      { W = fus_W;  P = fusWp;  N = DIM_; K = 4096;      off = i; }
    else if (i < e1) { W = W_ih;   P = Wihp;   N = G4_;  K = DIM_;      off = i - e0; }
    else if (i < e2) { W = W_hh;   P = Whhp;   N = G4_;  K = HID_;      off = i - e1; }
    else if (i < e3) { W = wq_W;   P = wqp;    N = DK_;  K = HID_;      off = i - e2; }
    else if (i < e4) { W = wk_W;   P = wkp;    N = DK_;  K = HID_;      off = i - e3; }
    else if (i < e5) {
        long o = i - e4;
        long hsz = (long)DK_ * HID_;
        int z = (int)(o / hsz);
        W = wv_W + (long)z * hsz; P = wvp + (long)z * hsz;
        N = DK_; K = HID_; off = o - (long)z * hsz;
    }
    else             { W = wout_W; P = woutp;  N = DK_;  K = NH_ * DK_; off = i - e5; }
    int k = (int)(off % K);
    int nn = (int)(off / K);
    int kg = k >> 4, nt = nn >> 3;
    int q2 = (k >> 3) & 1, pos = (k >> 2) & 1;
    int l = (nn & 7) * 4 + (k & 3);
    long o2 = ((((long)kg * (N >> 3) + nt) * 2 + q2) * 64) + l * 2 + pos;
    P[o2] = f2tf(W[off]);
}

__global__ void __launch_bounds__(256)
round_vec(const float* __restrict__ s, float* __restrict__ d, long n)
{
    long i = (long)blockIdx.x * 256 + threadIdx.x;
    if (i < n) d[i] = f2tf(s[i]);
}

// --------------------------- tf32 GEMM (round-9 champion) -------------------
__global__ void __launch_bounds__(256, 2)
tgemm(const float* __restrict__ A, int lda, long sAz,
      const float* __restrict__ Bp, long sBz, int N,
      float* __restrict__ C, int ldc, long sCz, int K,
      const float* __restrict__ bias, int sbz, int act, int rnd)
{
    extern __shared__ __align__(16) float dsm[];
    const int tid = threadIdx.x;
    const int m0 = blockIdx.y * MT;
    const int nt0 = blockIdx.x * 16;
    A  += (long)blockIdx.z * sAz;
    Bp += (long)blockIdx.z * sBz;
    C  += (long)blockIdx.z * sCz;
    const float* bz = bias ? bias + (long)blockIdx.z * sbz : (const float*)0;

    const int w = tid >> 5, lane = tid & 31;
    const int wm = w & 3, wn = w >> 2;
    const int gid = lane >> 2, tig = lane & 3;

    const unsigned sb = (unsigned)__cvta_generic_to_shared(dsm);
    const int NT8 = N >> 3;

    float acc[2][8][4];
    #pragma unroll
    for (int i = 0; i < 2; i++)
        #pragma unroll
        for (int j = 0; j < 8; j++)
            #pragma unroll
            for (int q = 0; q < 4; q++) acc[i][j][q] = 0.0f;

    const int KT = K / BK;

    const int ar = tid >> 3, ach = tid & 7;
    auto loadStage = [&](int stg, int k0) {
        const unsigned as = sb + (unsigned)stg * STG;
        #pragma unroll
        for (int i = 0; i < 4; i++) {
            int r = ar + i * 32;
            cpa16(as + (unsigned)(r * ASTR * 4 + ach * 16),
                  A + (long)(m0 + r) * lda + k0 + ach * 4);
        }
        const unsigned bs = as + ABYTES;
        const int kg0 = k0 >> 4;
        #pragma unroll
        for (int i = 0; i < 4; i++) {
            int g = i * 256 + tid;
            int kg2 = g >> 9, rest = g & 511;
            cpa16(bs + (unsigned)(kg2 * 8192 + rest * 16),
                  Bp + ((long)(kg0 + kg2) * NT8 + nt0) * 128 + rest * 4);
        }
    };

    loadStage(0, 0);
    cpa_commit();
    if (KT > 1) loadStage(1, BK);
    cpa_commit();

    const unsigned aoffL = (unsigned)((wm * 32 + (lane & 15)) * ASTR * 4 + (lane >> 4) * 16);
    const unsigned boffL = (unsigned)((wn * 8) * 512 + lane * 8);

    int stage = 0;
    for (int t = 0; t < KT; t++) {
        cpa_wait1();
        __syncthreads();
        const unsigned as = sb + (unsigned)stage * STG;
        const unsigned bs = as + ABYTES;
        #pragma unroll
        for (int kk = 0; kk < 4; kk++) {
            unsigned af0[4], af1[4];
            ldm4(af0, as + aoffL + kk * 32);
            ldm4(af1, as + aoffL + 16 * ASTR * 4 + kk * 32);
            const unsigned bb = bs + boffL + (kk >> 1) * 8192 + (kk & 1) * 256;
            #pragma unroll
            for (int j = 0; j < 8; j++) {
                unsigned b0, b1;
                lds2(b0, b1, bb + j * 512);
                mma_tf32(acc[0][j], af0, b0, b1);
                mma_tf32(acc[1][j], af1, b0, b1);
            }
        }
        if (t + 2 < KT) {
            int ns = stage + 2; if (ns >= NSTG) ns -= NSTG;
            loadStage(ns, (t + 2) * BK);
        }
        cpa_commit();
        if (++stage == NSTG) stage = 0;
    }

    const int n0 = nt0 * 8;
    #pragma unroll
    for (int i = 0; i < 2; i++) {
        const int r0 = m0 + wm * 32 + i * 16 + gid;
        #pragma unroll
        for (int j = 0; j < 8; j++) {
            const int col = n0 + wn * 64 + j * 8 + 2 * tig;
            float bx = 0.0f, by = 0.0f;
            if (bz) { bx = bz[col]; by = bz[col + 1]; }
            float v0x = acc[i][j][0] + bx, v0y = acc[i][j][1] + by;
            float v1x = acc[i][j][2] + bx, v1y = acc[i][j][3] + by;
            if (act) {
                v0x = fmaxf(v0x, 0.0f); v0y = fmaxf(v0y, 0.0f);
                v1x = fmaxf(v1x, 0.0f); v1y = fmaxf(v1y, 0.0f);
            }
            if (rnd) {
                v0x = f2tf(v0x); v0y = f2tf(v0y);
                v1x = f2tf(v1x); v1y = f2tf(v1y);
            }
            *(float2*)(C + (long)r0 * ldc + col) = make_float2(v0x, v0y);
            *(float2*)(C + (long)(r0 + 8) * ldc + col) = make_float2(v1x, v1y);
        }
    }
}

// --------------------- pointwise kernels ------------------------------------
__global__ void __launch_bounds__(256)
ln_rows_kernel(float* __restrict__ x, const float* __restrict__ g,
               const float* __restrict__ b)
{
    __shared__ float sx[G4_];
    long base = (long)blockIdx.x * G4_;
    float s = 0.0f, ss = 0.0f;
    for (int j = threadIdx.x; j < G4_; j += 256) {
        float v = x[base + j];
        sx[j] = v; s += v; ss += v * v;
    }
    float2 r = blockReduce2(s, ss);
    float mean = r.x * (1.0f / G4_);
    float var  = r.y * (1.0f / G4_) - mean * mean;
    float inv  = rsqrtf(var + EPS_);
    for (int j = threadIdx.x; j < G4_; j += 256)
        x[base + j] = (sx[j] - mean) * inv * g[j] + b[j];
}

__global__ void __launch_bounds__(256)
lstm_cell_kernel(const float* __restrict__ hw,
                 const float* __restrict__ gx,
                 const float* __restrict__ g_hh, const float* __restrict__ b_hh,
                 const float* __restrict__ g_c,  const float* __restrict__ b_c,
                 float* __restrict__ h, float* __restrict__ c,
                 float* __restrict__ lstm, int t)
{
    __shared__ float sg[G4_];
    const int b = blockIdx.x;
    const int tid = threadIdx.x;
    const float* row = hw + (long)b * G4_;
    float s = 0.0f, ss = 0.0f;
    for (int j = tid; j < G4_; j += 256) {
        float v = row[j];
        sg[j] = v; s += v; ss += v * v;
    }
    float2 r = blockReduce2(s, ss);
    float mean = r.x * (1.0f / G4_);
    float var  = r.y * (1.0f / G4_) - mean * mean;
    float inv  = rsqrtf(var + EPS_);

    const float* gxr = gx + ((long)b * SEQ_ + t) * G4_;
    float cval[2];
    float sc = 0.0f, ssc = 0.0f;
    #pragma unroll
    for (int rr = 0; rr < 2; rr++) {
        int j = rr * 256 + tid;
        float gi = (sg[j]        - mean) * inv * g_hh[j]        + b_hh[j]        + gxr[j];
        float gf = (sg[512 + j]  - mean) * inv * g_hh[512 + j]  + b_hh[512 + j]  + gxr[512 + j];
        float gg = (sg[1024 + j] - mean) * inv * g_hh[1024 + j] + b_hh[1024 + j] + gxr[1024 + j];
        float cn = sigm(gf) * c[(long)b * HID_ + j] + sigm(gi) * tanhf(gg);
        cval[rr] = cn;
        c[(long)b * HID_ + j] = cn;
        sc += cn; ssc += cn * cn;
    }
    float2 rc = blockReduce2(sc, ssc);
    float meanc = rc.x * (1.0f / HID_);
    float varc  = rc.y * (1.0f / HID_) - meanc * meanc;
    float invc  = rsqrtf(varc + EPS_);
    #pragma unroll
    for (int rr = 0; rr < 2; rr++) {
        int j = rr * 256 + tid;
        float go = (sg[1536 + j] - mean) * inv * g_hh[1536 + j] + b_hh[1536 + j] + gxr[1536 + j];
        float hn = sigm(go) * tanhf((cval[rr] - meanc) * invc * g_c[j] + b_c[j]);
        hn = f2tf(hn);
        h[(long)b * HID_ + j] = hn;
        lstm[((long)b * SEQ_ + t) * HID_ + j] = hn;
    }
}

__global__ void __launch_bounds__(128)
attn_kernel(const float* __restrict__ kall, const float* __restrict__ qb,
            const float* __restrict__ lstm, float* __restrict__ mbuf)
{
    const int hidx = blockIdx.x;
    const int b    = blockIdx.y;
    const int tid  = threadIdx.x;
    __shared__ float ssc[SEQ_];
    __shared__ float wsum[SEQ_][4];

    float qv = qb[(long)b * DK_ + hidx * DH_ + tid];
    int w = tid >> 5, l = tid & 31;
    for (int s = 0; s < SEQ_; s++) {
        float v = kall[((long)b * SEQ_ + s) * DK_ + hidx * DH_ + tid] * qv;
        #pragma unroll
        for (int o = 16; o > 0; o >>= 1) v += __shfl_down_sync(0xffffffffu, v, o);
        if (l == 0) wsum[s][w] = v;
    }
    __syncthreads();
    if (tid < SEQ_) {
        float sc = wsum[tid][0] + wsum[tid][1] + wsum[tid][2] + wsum[tid][3];
        ssc[tid] = sc * 0.08838834764831845f;
    }
    __syncthreads();

    float e[SEQ_];
    float mx = -1e30f;
    #pragma unroll
    for (int s = 0; s < SEQ_; s++) mx = fmaxf(mx, ssc[s]);
    float den = 0.0f;
    #pragma unroll
    for (int s = 0; s < SEQ_; s++) { e[s] = expf(ssc[s] - mx); den += e[s]; }
    float dinv = 1.0f / den;

    #pragma unroll
    for (int rr = 0; rr < HID_ / 128; rr++) {
        int d = rr * 128 + tid;
        float acc = 0.0f;
        #pragma unroll
        for (int s = 0; s < SEQ_; s++)
            acc += e[s] * lstm[((long)b * SEQ_ + s) * HID_ + d];
        mbuf[((long)b * NH_ + hidx) * HID_ + d] = f2tf(acc * dinv);
    }
}

__global__ void __launch_bounds__(256)
out_final_kernel(const float* __restrict__ oh, const float* __restrict__ outW,
                 const float* __restrict__ outb, const float* __restrict__ label,
                 float* __restrict__ out, float* __restrict__ diff)
{
    int w = threadIdx.x >> 5, l = threadIdx.x & 31;
    int b = blockIdx.x * 8 + w;
    float s = 0.0f;
    for (int j = l; j < DK_; j += 32) s += oh[(long)b * DK_ + j] * outW[j];
    #pragma unroll
    for (int o = 16; o > 0; o >>= 1) s += __shfl_down_sync(0xffffffffu, s, o);
    if (l == 0) {
        float v = s + outb[0];
        out[1 + b] = v;
        float d = v - label[(long)b * SEQ_ + (SEQ_ - 1)];
        diff[b] = d * d;
    }
}

__global__ void __launch_bounds__(256)
loss_kernel(const float* __restrict__ diff, float* __restrict__ out)
{
    float s = 0.0f;
    for (int j = threadIdx.x; j < B_; j += 256) s += diff[j];
    float2 r = blockReduce2(s, 0.0f);
    if (threadIdx.x == 0) out[0] = r.x * (1.0f / B_);
}

// ------------------------------- launch -------------------------------------
static inline void getp(void** p, const void* sym) { cudaGetSymbolAddress(p, sym); }

extern "C" void kernel_launch(void* const* d_in, const int* in_sizes, int n_in,
                              void* d_out, int out_size)
{
    const float* visual = (const float*)d_in[0];
    const float* text   = (const float*)d_in[1];
    const float* user   = (const float*)d_in[2];
    const float* cat    = (const float*)d_in[3];
    const float* label  = (const float*)d_in[4];
    const float* h0     = (const float*)d_in[5];
    const float* c0     = (const float*)d_in[6];
    const float* fus_W  = (const float*)d_in[7];
    const float* fus_b  = (const float*)d_in[8];
    const float* W_ih   = (const float*)d_in[9];
    const float* W_hh   = (const float*)d_in[10];
    const float* g_ih   = (const float*)d_in[11];
    const float* b_ih   = (const float*)d_in[12];
    const float* g_hh   = (const float*)d_in[13];
    const float* b_hh   = (const float*)d_in[14];
    const float* g_c    = (const float*)d_in[15];
    const float* b_c    = (const float*)d_in[16];
    const float* wq_W   = (const float*)d_in[17];
    const float* wq_b   = (const float*)d_in[18];
    const float* wk_W   = (const float*)d_in[19];
    const float* wk_b   = (const float*)d_in[20];
    const float* wv_W   = (const float*)d_in[21];
    const float* wv_b   = (const float*)d_in[22];
    const float* wout_W = (const float*)d_in[23];
    const float* wout_b = (const float*)d_in[24];
    const float* out_W  = (const float*)d_in[25];
    const float* out_b  = (const float*)d_in[26];
    float* out = (float*)d_out;

    float *mods, *fusWp, *Wihp, *Whhp, *wqp, *wkp, *wvp, *woutp;
    float *vt, *gx, *hw, *h, *c, *lstm, *kall, *qb, *m, *ctx, *oh, *diff;
    getp((void**)&mods,  d_mods);  getp((void**)&fusWp, d_fusWp);
    getp((void**)&Wihp,  d_Wihp);  getp((void**)&Whhp,  d_Whhp);
    getp((void**)&wqp,   d_wqp);   getp((void**)&wkp,   d_wkp);
    getp((void**)&wvp,   d_wvp);   getp((void**)&woutp, d_woutp);
    getp((void**)&vt,    d_vt);    getp((void**)&gx,    d_gx);
    getp((void**)&hw,    d_hw);    getp((void**)&h,     d_h);
    getp((void**)&c,     d_c);     getp((void**)&lstm,  d_lstm);
    getp((void**)&kall,  d_kall);  getp((void**)&qb,    d_qb);
    getp((void**)&m,     d_m);     getp((void**)&ctx,   d_ctx);
    getp((void**)&oh,    d_oh);    getp((void**)&diff,  d_diff);

    cudaFuncSetAttribute(tgemm, cudaFuncAttributeMaxDynamicSharedMemorySize, SMEM_G);

    // 0. producers
    {
        long nthr = (long)BS_ * 4096 / 4;
        conv_concat<<<(unsigned)((nthr + 255) / 256), 256>>>(visual, text, user, cat, mods);
    }
    {
        long total = SZ_FUS + SZ_IH + SZ_HH + 2 * SZ_QK + SZ_WV + SZ_OUT;
        perm_all<<<(unsigned)((total + 255) / 256), 256>>>(
            fus_W, W_ih, W_hh, wq_W, wk_W, wv_W, wout_W,
            fusWp, Wihp, Whhp, wqp, wkp, wvp, woutp);
    }
    round_vec<<<(B_ * HID_ + 255) / 256, 256>>>(h0, h, (long)B_ * HID_);
    cudaMemcpyAsync(c, c0, (size_t)B_ * HID_ * sizeof(float), cudaMemcpyDeviceToDevice, 0);

    // 1. fusion GEMM + relu -> vt (rounded)   (32768 x 1024 x 4096)
    tgemm<<<dim3(DIM_ / NT, BS_ / MT), 256, SMEM_G>>>(
        mods, 4096, 0, fusWp, 0, DIM_, vt, DIM_, 0, 4096, fus_b, 0, 1, 1);

    // 2. gx = vt @ W_ih^T  (32768 x 2048 x 1024)
    tgemm<<<dim3(G4_ / NT, BS_ / MT), 256, SMEM_G>>>(
        vt, DIM_, 0, Wihp, 0, G4_, gx, G4_, 0, DIM_, (const float*)0, 0, 0, 0);

    // 3. LSTM recurrence. First h@W_hh GEMM depends only on h, so it is
    //    issued BEFORE ln_rows (which must finish before cell t=0; stream
    //    order guarantees that). This puts a tgemm at launch slot 6 for ncu.
    tgemm<<<dim3(G4_ / NT, B_ / MT), 256, SMEM_G>>>(
        h, HID_, 0, Whhp, 0, G4_, hw, G4_, 0, HID_, (const float*)0, 0, 0, 0);
    ln_rows_kernel<<<BS_, 256>>>(gx, g_ih, b_ih);
    lstm_cell_kernel<<<B_, 256>>>(hw, gx, g_hh, b_hh, g_c, b_c, h, c, lstm, 0);
    for (int t = 1; t < SEQ_; t++) {
        tgemm<<<dim3(G4_ / NT, B_ / MT), 256, SMEM_G>>>(
            h, HID_, 0, Whhp, 0, G4_, hw, G4_, 0, HID_, (const float*)0, 0, 0, 0);
        lstm_cell_kernel<<<B_, 256>>>(hw, gx, g_hh, b_hh, g_c, b_c, h, c, lstm, t);
    }

    // 4. k / q projections
    tgemm<<<dim3(DK_ / NT, BS_ / MT), 256, SMEM_G>>>(
        lstm, HID_, 0, wkp, 0, DK_, kall, DK_, 0, HID_, wk_b, 0, 0, 0);
    tgemm<<<dim3(DK_ / NT, B_ / MT), 256, SMEM_G>>>(
        h, HID_, 0, wqp, 0, DK_, qb, DK_, 0, HID_, wq_b, 0, 0, 0);

    // 5. attention -> m (rounded)
    attn_kernel<<<dim3(NH_, B_), 128>>>(kall, qb, lstm, m);

    // 6. ctx = wv_W . m  (batched over heads, rounded)
    tgemm<<<dim3(DK_ / NT, B_ / MT, NH_), 256, SMEM_G>>>(
        m, NH_ * HID_, HID_, wvp, (long)DK_ * HID_, DK_,
        ctx, NH_ * DK_, DK_, HID_, wv_b, DK_, 0, 1);

    // 7. out_h = ctx @ wout_W^T  (2048 x 512 x 2048)
    tgemm<<<dim3(DK_ / NT, B_ / MT), 256, SMEM_G>>>(
        ctx, NH_ * DK_, 0, woutp, 0, DK_, oh, DK_, 0, NH_ * DK_, wout_b, 0, 0, 0);

    // 8. final projection + loss
    out_final_kernel<<<B_ / 8, 256>>>(oh, out_W, out_b, label, out, diff);
    loss_kernel<<<1, 256>>>(diff, out);
}